// round 1
// baseline (speedup 1.0000x reference)
#include <cuda_runtime.h>

#define WS   7
#define NTOK 49          // ws*ws
#define C    128
#define NH   4
#define HD   32
#define TPB  384

// smem: xs (49*128, reused as attention output) | qs | ks | vs | bias (169*4)
#define SM_FLOATS (4 * NTOK * C + 169 * NH)
#define SM_BYTES  (SM_FLOATS * 4)

__global__ __launch_bounds__(TPB, 2)
void win_attn_kernel(const float* __restrict__ x,
                     const float* __restrict__ qkv_w,
                     const float* __restrict__ qkv_b,
                     const float* __restrict__ proj_w,
                     const float* __restrict__ proj_b,
                     const float* __restrict__ bt,
                     float* __restrict__ out)
{
    extern __shared__ float sm[];
    float* xs  = sm;                 // 49*128, later reused as attn-out
    float* qs  = sm + NTOK * C;
    float* ks  = sm + 2 * NTOK * C;
    float* vs  = sm + 3 * NTOK * C;
    float* bts = sm + 4 * NTOK * C;  // 169*4

    const int t   = threadIdx.x;
    const int blk = blockIdx.x;
    const int b   = blk >> 6;
    const int win = blk & 63;
    const int wy  = win >> 3;
    const int wx  = win & 7;

    // base offset of x[b][wy*7][wx*7][0]
    const long base = (((long)b * 56 + wy * 7) * 56 + wx * 7) * C;

    // ---- stage bias table ----
    for (int i = t; i < 169 * NH; i += TPB) bts[i] = bt[i];

    // ---- stage window x into smem (float4, coalesced) ----
    for (int idx = t; idx < NTOK * (C / 4); idx += TPB) {
        int r  = idx / (C / 4);
        int k4 = idx - r * (C / 4);
        int iy = r / WS, ix = r - iy * WS;
        float4 v = *(const float4*)(x + base + ((long)iy * 56 + ix) * C + k4 * 4);
        ((float4*)xs)[r * (C / 4) + k4] = v;
    }
    __syncthreads();

    // ---- QKV GEMM: thread t owns output column c = t (of 384) ----
    {
        const int c = t;
        float acc[NTOK];
        #pragma unroll
        for (int r = 0; r < NTOK; r++) acc[r] = 0.f;

        float w0 = qkv_w[0 * 384 + c];
        float w1 = qkv_w[1 * 384 + c];
        float w2 = qkv_w[2 * 384 + c];
        float w3 = qkv_w[3 * 384 + c];

        for (int k = 0; k < C; k += 4) {
            const int kn = (k + 4 < C) ? (k + 4) : k;   // prefetch next weights
            float n0 = qkv_w[(kn + 0) * 384 + c];
            float n1 = qkv_w[(kn + 1) * 384 + c];
            float n2 = qkv_w[(kn + 2) * 384 + c];
            float n3 = qkv_w[(kn + 3) * 384 + c];
            const float4* xr = ((const float4*)xs) + (k >> 2);
            #pragma unroll
            for (int r = 0; r < NTOK; r++) {
                float4 xv = xr[r * (C / 4)];    // warp-uniform -> LDS broadcast
                acc[r] = fmaf(xv.x, w0, acc[r]);
                acc[r] = fmaf(xv.y, w1, acc[r]);
                acc[r] = fmaf(xv.z, w2, acc[r]);
                acc[r] = fmaf(xv.w, w3, acc[r]);
            }
            w0 = n0; w1 = n1; w2 = n2; w3 = n3;
        }

        const float bb = qkv_b[c];
        float* dst = (c < 128) ? qs : ((c < 256) ? ks : vs);
        const int cc = c & 127;
        #pragma unroll
        for (int r = 0; r < NTOK; r++) dst[r * C + cc] = acc[r] + bb;
    }
    __syncthreads();

    // ---- attention: threads 0..195 -> (head h, query i) ----
    if (t < NH * NTOK) {
        const int h  = t / NTOK;
        const int i  = t - h * NTOK;
        const int iy = i / WS, ix = i - iy * WS;
        const float scale = 0.17677669529663687f;   // 32^-0.5

        float4 qv[HD / 4];
        #pragma unroll
        for (int d = 0; d < HD / 4; d++)
            qv[d] = ((const float4*)(qs + i * C + h * HD))[d];

        float4 ov[HD / 4];
        #pragma unroll
        for (int d = 0; d < HD / 4; d++) ov[d] = make_float4(0.f, 0.f, 0.f, 0.f);
        float l = 0.f;

        int jy = 0, jx = 0;
        for (int j = 0; j < NTOK; j++) {
            const float4* kv = (const float4*)(ks + j * C + h * HD);
            float s = 0.f;
            #pragma unroll
            for (int d = 0; d < HD / 4; d++) {
                float4 kk = kv[d];
                s = fmaf(qv[d].x, kk.x, s);
                s = fmaf(qv[d].y, kk.y, s);
                s = fmaf(qv[d].z, kk.z, s);
                s = fmaf(qv[d].w, kk.w, s);
            }
            const int ridx = (iy - jy + 6) * 13 + (ix - jx + 6);
            s = fmaf(s, scale, bts[ridx * NH + h]);
            const float p = __expf(s);   // |s| small: no max-subtract needed
            l += p;
            const float4* vv = (const float4*)(vs + j * C + h * HD);
            #pragma unroll
            for (int d = 0; d < HD / 4; d++) {
                float4 v4 = vv[d];
                ov[d].x = fmaf(p, v4.x, ov[d].x);
                ov[d].y = fmaf(p, v4.y, ov[d].y);
                ov[d].z = fmaf(p, v4.z, ov[d].z);
                ov[d].w = fmaf(p, v4.w, ov[d].w);
            }
            if (++jx == WS) { jx = 0; ++jy; }
        }

        const float inv = 1.f / l;
        float4* ao = (float4*)(xs + i * C + h * HD);   // reuse xs buffer
        #pragma unroll
        for (int d = 0; d < HD / 4; d++) {
            ov[d].x *= inv; ov[d].y *= inv; ov[d].z *= inv; ov[d].w *= inv;
            ao[d] = ov[d];
        }
    }
    __syncthreads();

    // ---- proj GEMM: c = t%128, row group g = t/128 owns rows g*17.. ----
    {
        const int c  = t & 127;
        const int g  = t >> 7;           // 0..2
        const int r0 = g * 17;           // rows r0..r0+16 (reads past 48 are safe smem)

        float acc[17];
        #pragma unroll
        for (int r = 0; r < 17; r++) acc[r] = 0.f;

        float w0 = proj_w[0 * C + c];
        float w1 = proj_w[1 * C + c];
        float w2 = proj_w[2 * C + c];
        float w3 = proj_w[3 * C + c];

        for (int k = 0; k < C; k += 4) {
            const int kn = (k + 4 < C) ? (k + 4) : k;
            float n0 = proj_w[(kn + 0) * C + c];
            float n1 = proj_w[(kn + 1) * C + c];
            float n2 = proj_w[(kn + 2) * C + c];
            float n3 = proj_w[(kn + 3) * C + c];
            const float4* ar = ((const float4*)xs) + (long)r0 * (C / 4) + (k >> 2);
            #pragma unroll
            for (int r = 0; r < 17; r++) {
                float4 av = ar[r * (C / 4)];   // warp-uniform broadcast
                acc[r] = fmaf(av.x, w0, acc[r]);
                acc[r] = fmaf(av.y, w1, acc[r]);
                acc[r] = fmaf(av.z, w2, acc[r]);
                acc[r] = fmaf(av.w, w3, acc[r]);
            }
            w0 = n0; w1 = n1; w2 = n2; w3 = n3;
        }

        const float bb = proj_b[c];
        #pragma unroll
        for (int r = 0; r < 17; r++) {
            const int rr = r0 + r;
            if (rr < NTOK) {
                const int iy = rr / WS, ix = rr - iy * WS;
                out[base + ((long)iy * 56 + ix) * C + c] = acc[r] + bb;
            }
        }
    }
}

extern "C" void kernel_launch(void* const* d_in, const int* in_sizes, int n_in,
                              void* d_out, int out_size)
{
    const float* x      = (const float*)d_in[0];
    const float* qkv_w  = (const float*)d_in[1];
    const float* qkv_b  = (const float*)d_in[2];
    const float* proj_w = (const float*)d_in[3];
    const float* proj_b = (const float*)d_in[4];
    const float* bt     = (const float*)d_in[5];
    float* out = (float*)d_out;

    cudaFuncSetAttribute(win_attn_kernel,
                         cudaFuncAttributeMaxDynamicSharedMemorySize, SM_BYTES);

    // 64 images * 8*8 windows = 4096 CTAs
    win_attn_kernel<<<4096, TPB, SM_BYTES>>>(x, qkv_w, qkv_b, proj_w, proj_b, bt, out);
}

// round 2
// speedup vs baseline: 1.1599x; 1.1599x over previous
#include <cuda_runtime.h>

#define WS   7
#define NTOK 49
#define C    128
#define NH   4
#define HD   32
#define TPB  384

#define SM_FLOATS (4 * NTOK * C + 169 * NH)
#define SM_BYTES  (SM_FLOATS * 4)

typedef unsigned long long u64;

// k-pair-interleaved weights: element [kp*COLS + c] = (w[2kp][c], w[2kp+1][c])
__device__ u64 g_qkv_wp[64 * 384];
__device__ u64 g_proj_wp[64 * 128];

__global__ void repack_kernel(const float* __restrict__ qw,
                              const float* __restrict__ pw)
{
    int i = blockIdx.x * 256 + threadIdx.x;
    if (i < 64 * 384) {
        int kp = i / 384, c = i - kp * 384;
        float lo = qw[(2 * kp) * 384 + c];
        float hi = qw[(2 * kp + 1) * 384 + c];
        u64 v; asm("mov.b64 %0,{%1,%2};" : "=l"(v) : "f"(lo), "f"(hi));
        g_qkv_wp[i] = v;
    }
    if (i < 64 * 128) {
        int kp = i / 128, c = i - kp * 128;
        float lo = pw[(2 * kp) * 128 + c];
        float hi = pw[(2 * kp + 1) * 128 + c];
        u64 v; asm("mov.b64 %0,{%1,%2};" : "=l"(v) : "f"(lo), "f"(hi));
        g_proj_wp[i] = v;
    }
}

__device__ __forceinline__ void lds_v2(u64& a, u64& b, unsigned saddr) {
    asm volatile("ld.shared.v2.b64 {%0,%1}, [%2];" : "=l"(a), "=l"(b) : "r"(saddr));
}
__device__ __forceinline__ void ldg_v2(u64& a, u64& b, const u64* p) {
    asm volatile("ld.global.nc.v2.b64 {%0,%1}, [%2];" : "=l"(a), "=l"(b) : "l"(p));
}
__device__ __forceinline__ void fma2(u64& d, u64 a, u64 b) {
    asm("fma.rn.f32x2 %0, %1, %2, %0;" : "+l"(d) : "l"(a), "l"(b));
}
__device__ __forceinline__ float red2(u64 a) {
    float lo, hi; asm("mov.b64 {%0,%1}, %2;" : "=f"(lo), "=f"(hi) : "l"(a));
    return lo + hi;
}
__device__ __forceinline__ u64 pack2(float lo, float hi) {
    u64 r; asm("mov.b64 %0,{%1,%2};" : "=l"(r) : "f"(lo), "f"(hi));
    return r;
}
__device__ __forceinline__ void unpack2(float& lo, float& hi, u64 a) {
    asm("mov.b64 {%0,%1}, %2;" : "=f"(lo), "=f"(hi) : "l"(a));
}

__global__ __launch_bounds__(TPB, 1)
void win_attn_kernel(const float* __restrict__ x,
                     const float* __restrict__ qkv_b,
                     const float* __restrict__ proj_b,
                     const float* __restrict__ bt,
                     float* __restrict__ out)
{
    extern __shared__ float sm[];
    float* xs  = sm;                 // 49*128, later reused as attn output
    float* qs  = sm + NTOK * C;
    float* ks  = sm + 2 * NTOK * C;
    float* vs  = sm + 3 * NTOK * C;
    float* bts = sm + 4 * NTOK * C;  // 169*4

    const unsigned xs_a  = (unsigned)__cvta_generic_to_shared(xs);
    const unsigned qs_a  = (unsigned)__cvta_generic_to_shared(qs);
    const unsigned ks_a  = (unsigned)__cvta_generic_to_shared(ks);
    const unsigned vs_a  = (unsigned)__cvta_generic_to_shared(vs);

    const int t   = threadIdx.x;
    const int blk = blockIdx.x;
    const int b   = blk >> 6;
    const int win = blk & 63;
    const int wy  = win >> 3;
    const int wx  = win & 7;
    const long base = (((long)b * 56 + wy * 7) * 56 + wx * 7) * C;

    for (int i = t; i < 169 * NH; i += TPB) bts[i] = bt[i];

    for (int idx = t; idx < NTOK * (C / 4); idx += TPB) {
        int r  = idx / (C / 4);
        int k4 = idx - r * (C / 4);
        int iy = r / WS, ix = r - iy * WS;
        float4 v = *(const float4*)(x + base + ((long)iy * 56 + ix) * C + k4 * 4);
        ((float4*)xs)[r * (C / 4) + k4] = v;
    }
    __syncthreads();

    // ================= QKV GEMM: thread = 4 cols (c0..c0+3) x 13 rows =================
    {
        const int cg = t % 96, rg = t / 96;          // warp-uniform rg
        const int c0 = cg * 4, r0 = rg * 13;
        const unsigned xrow = xs_a + r0 * (C * 4);

        u64 acc[13][4];
        #pragma unroll
        for (int r = 0; r < 13; r++)
            #pragma unroll
            for (int j = 0; j < 4; j++) acc[r][j] = 0ull;

        const u64* wq = g_qkv_wp;
        for (int kp2 = 0; kp2 < 32; kp2++) {
            const int kp = kp2 * 2;
            u64 wa0, wa1, wa2, wa3, wb0, wb1, wb2, wb3;
            ldg_v2(wa0, wa1, wq + kp * 384 + c0);
            ldg_v2(wa2, wa3, wq + kp * 384 + c0 + 2);
            ldg_v2(wb0, wb1, wq + (kp + 1) * 384 + c0);
            ldg_v2(wb2, wb3, wq + (kp + 1) * 384 + c0 + 2);
            #pragma unroll
            for (int r = 0; r < 13; r++) {
                u64 xa, xb;
                lds_v2(xa, xb, xrow + r * (C * 4) + kp2 * 16);  // uniform -> broadcast
                fma2(acc[r][0], xa, wa0);
                fma2(acc[r][1], xa, wa1);
                fma2(acc[r][2], xa, wa2);
                fma2(acc[r][3], xa, wa3);
                fma2(acc[r][0], xb, wb0);
                fma2(acc[r][1], xb, wb1);
                fma2(acc[r][2], xb, wb2);
                fma2(acc[r][3], xb, wb3);
            }
        }

        const float4 bb = *(const float4*)(qkv_b + c0);
        float* dst = (c0 < 128) ? qs : ((c0 < 256) ? ks : vs);
        const int cc = c0 & 127;
        #pragma unroll
        for (int r = 0; r < 13; r++) {
            const int row = r0 + r;
            if (row < NTOK) {
                float4 o;
                o.x = red2(acc[r][0]) + bb.x;
                o.y = red2(acc[r][1]) + bb.y;
                o.z = red2(acc[r][2]) + bb.z;
                o.w = red2(acc[r][3]) + bb.w;
                *(float4*)(dst + row * C + cc) = o;
            }
        }
    }
    __syncthreads();

    // ================= attention: threads 0..195 = (head, query) =================
    if (t < NH * NTOK) {
        const int h  = t / NTOK;
        const int i  = t - h * NTOK;
        const int iy = i / WS, ix = i - iy * WS;
        const float scale = 0.17677669529663687f;   // 32^-0.5

        u64 qv[16];
        {
            const unsigned qa = qs_a + (i * C + h * HD) * 4;
            #pragma unroll
            for (int d = 0; d < 16; d += 2) lds_v2(qv[d], qv[d + 1], qa + d * 8);
        }

        u64 ov[16];
        #pragma unroll
        for (int d = 0; d < 16; d++) ov[d] = 0ull;
        float l = 0.f;

        int jy = 0, jx = 0;
        for (int j = 0; j < NTOK; j++) {
            const unsigned ka = ks_a + (j * C + h * HD) * 4;
            u64 s0 = 0ull, s1 = 0ull, s2 = 0ull, s3 = 0ull;
            {
                u64 k0, k1, k2, k3;
                lds_v2(k0, k1, ka);       fma2(s0, qv[0],  k0); fma2(s1, qv[1],  k1);
                lds_v2(k2, k3, ka + 16);  fma2(s2, qv[2],  k2); fma2(s3, qv[3],  k3);
                lds_v2(k0, k1, ka + 32);  fma2(s0, qv[4],  k0); fma2(s1, qv[5],  k1);
                lds_v2(k2, k3, ka + 48);  fma2(s2, qv[6],  k2); fma2(s3, qv[7],  k3);
                lds_v2(k0, k1, ka + 64);  fma2(s0, qv[8],  k0); fma2(s1, qv[9],  k1);
                lds_v2(k2, k3, ka + 80);  fma2(s2, qv[10], k2); fma2(s3, qv[11], k3);
                lds_v2(k0, k1, ka + 96);  fma2(s0, qv[12], k0); fma2(s1, qv[13], k1);
                lds_v2(k2, k3, ka + 112); fma2(s2, qv[14], k2); fma2(s3, qv[15], k3);
            }
            float s = (red2(s0) + red2(s1)) + (red2(s2) + red2(s3));
            const int ridx = (iy - jy + 6) * 13 + (ix - jx + 6);
            s = fmaf(s, scale, bts[ridx * NH + h]);
            const float p = __expf(s);
            l += p;
            const u64 pp = pack2(p, p);

            const unsigned va = vs_a + (j * C + h * HD) * 4;
            #pragma unroll
            for (int d = 0; d < 16; d += 2) {
                u64 v0, v1;
                lds_v2(v0, v1, va + d * 8);
                fma2(ov[d],     pp, v0);
                fma2(ov[d + 1], pp, v1);
            }
            if (++jx == WS) { jx = 0; ++jy; }
        }

        const float inv = 1.f / l;
        float* ao = xs + i * C + h * HD;     // reuse xs
        #pragma unroll
        for (int d = 0; d < 16; d += 2) {
            float a0, a1, a2, a3;
            unpack2(a0, a1, ov[d]);
            unpack2(a2, a3, ov[d + 1]);
            float4 o = make_float4(a0 * inv, a1 * inv, a2 * inv, a3 * inv);
            *(float4*)(ao + d * 2) = o;
        }
    }
    __syncthreads();

    // ================= proj GEMM: thread = 4 cols x 5 rows =================
    {
        const int cg = t & 31, rg = t >> 5;          // warp-uniform rg
        const int c0 = cg * 4, r0 = rg * 5;
        if (r0 < NTOK) {
            const unsigned xrow = xs_a + r0 * (C * 4);

            u64 acc[5][4];
            #pragma unroll
            for (int r = 0; r < 5; r++)
                #pragma unroll
                for (int j = 0; j < 4; j++) acc[r][j] = 0ull;

            const u64* wp = g_proj_wp;
            for (int kp2 = 0; kp2 < 32; kp2++) {
                const int kp = kp2 * 2;
                u64 wa0, wa1, wa2, wa3, wb0, wb1, wb2, wb3;
                ldg_v2(wa0, wa1, wp + kp * 128 + c0);
                ldg_v2(wa2, wa3, wp + kp * 128 + c0 + 2);
                ldg_v2(wb0, wb1, wp + (kp + 1) * 128 + c0);
                ldg_v2(wb2, wb3, wp + (kp + 1) * 128 + c0 + 2);
                #pragma unroll
                for (int r = 0; r < 5; r++) {
                    u64 xa, xb;
                    lds_v2(xa, xb, xrow + r * (C * 4) + kp2 * 16);
                    fma2(acc[r][0], xa, wa0);
                    fma2(acc[r][1], xa, wa1);
                    fma2(acc[r][2], xa, wa2);
                    fma2(acc[r][3], xa, wa3);
                    fma2(acc[r][0], xb, wb0);
                    fma2(acc[r][1], xb, wb1);
                    fma2(acc[r][2], xb, wb2);
                    fma2(acc[r][3], xb, wb3);
                }
            }

            const float4 bb = *(const float4*)(proj_b + c0);
            #pragma unroll
            for (int r = 0; r < 5; r++) {
                const int rr = r0 + r;
                if (rr < NTOK) {
                    const int iy = rr / WS, ix = rr - iy * WS;
                    float4 o;
                    o.x = red2(acc[r][0]) + bb.x;
                    o.y = red2(acc[r][1]) + bb.y;
                    o.z = red2(acc[r][2]) + bb.z;
                    o.w = red2(acc[r][3]) + bb.w;
                    *(float4*)(out + base + ((long)iy * 56 + ix) * C + c0) = o;
                }
            }
        }
    }
}

extern "C" void kernel_launch(void* const* d_in, const int* in_sizes, int n_in,
                              void* d_out, int out_size)
{
    const float* x      = (const float*)d_in[0];
    const float* qkv_w  = (const float*)d_in[1];
    const float* qkv_b  = (const float*)d_in[2];
    const float* proj_w = (const float*)d_in[3];
    const float* proj_b = (const float*)d_in[4];
    const float* bt     = (const float*)d_in[5];
    float* out = (float*)d_out;

    repack_kernel<<<(64 * 384 + 255) / 256, 256>>>(qkv_w, proj_w);

    cudaFuncSetAttribute(win_attn_kernel,
                         cudaFuncAttributeMaxDynamicSharedMemorySize, SM_BYTES);
    win_attn_kernel<<<4096, TPB, SM_BYTES>>>(x, qkv_b, proj_b, bt, out);
}

// round 4
// speedup vs baseline: 2.6865x; 2.3161x over previous
#include <cuda_runtime.h>

typedef unsigned int u32;
typedef unsigned long long u64;

#define TPB 256
#define RSTRIDE 132                      // row stride in words (conflict-free pad)

// smem byte offsets
#define XQ_OFF 0                         // X tile -> later Q -> later attn-out A tile (64*132*4)
#define KS_OFF 33792                     // K 49*132*4
#define VS_OFF 59664                     // V 49*132*4
#define BT_OFF 85536                     // bias table 676*4
#define SMB    88240

// pre-packed B fragments: [phase q,k,v,proj][ntile 16][kstep 16][lane 32] -> u64(b0,b1)
__device__ u64 g_B[4 * 8192];

__device__ __forceinline__ u32 cvt_tf32(float f) {
    u32 u; asm("cvt.rna.tf32.f32 %0, %1;" : "=r"(u) : "f"(f)); return u;
}

__global__ void repack(const float* __restrict__ qw, const float* __restrict__ pw)
{
    int i = blockIdx.x * 256 + threadIdx.x;       // 32768 total
    if (i >= 32768) return;
    int phase = i >> 13;
    int rem   = i & 8191;
    int nt    = rem >> 9;
    int ks    = (rem >> 5) & 15;
    int lane  = rem & 31;
    int k0 = ks * 8 + (lane & 3);
    int n  = nt * 8 + (lane >> 2);
    float f0, f1;
    if (phase < 3) { f0 = qw[k0 * 384 + phase * 128 + n]; f1 = qw[(k0 + 4) * 384 + phase * 128 + n]; }
    else           { f0 = pw[k0 * 128 + n];               f1 = pw[(k0 + 4) * 128 + n]; }
    g_B[i] = ((u64)cvt_tf32(f1) << 32) | (u64)cvt_tf32(f0);
}

// ---------------- helpers ----------------
__device__ __forceinline__ u32 lds32(u32 a) {
    u32 v; asm volatile("ld.shared.b32 %0, [%1];" : "=r"(v) : "r"(a)); return v;
}
__device__ __forceinline__ float lds32f(u32 a) {
    float v; asm volatile("ld.shared.f32 %0, [%1];" : "=f"(v) : "r"(a)); return v;
}
__device__ __forceinline__ void sts64(u32 a, float x, float y) {
    asm volatile("st.shared.v2.f32 [%0], {%1,%2};" :: "r"(a), "f"(x), "f"(y) : "memory");
}
__device__ __forceinline__ void sts128(u32 a, u32 x, u32 y, u32 z, u32 w) {
    asm volatile("st.shared.v4.b32 [%0], {%1,%2,%3,%4};" :: "r"(a), "r"(x), "r"(y), "r"(z), "r"(w) : "memory");
}
__device__ __forceinline__ void lds16(u64& a, u64& b, u32 saddr) {
    asm volatile("ld.shared.v2.b64 {%0,%1}, [%2];" : "=l"(a), "=l"(b) : "r"(saddr));
}
__device__ __forceinline__ void ldgB(u32& b0, u32& b1, const u64* p) {
    asm volatile("ld.global.nc.v2.u32 {%0,%1}, [%2];" : "=r"(b0), "=r"(b1) : "l"(p));
}
__device__ __forceinline__ void fma2(u64& d, u64 a, u64 b) {
    asm("fma.rn.f32x2 %0, %1, %2, %0;" : "+l"(d) : "l"(a), "l"(b));
}
__device__ __forceinline__ void mul2(u64& d, u64 a) {
    asm("mul.rn.f32x2 %0, %0, %1;" : "+l"(d) : "l"(a));
}
__device__ __forceinline__ float red2(u64 a) {
    float lo, hi; asm("mov.b64 {%0,%1}, %2;" : "=f"(lo), "=f"(hi) : "l"(a)); return lo + hi;
}
__device__ __forceinline__ u64 pack2(float lo, float hi) {
    u64 r; asm("mov.b64 %0,{%1,%2};" : "=l"(r) : "f"(lo), "f"(hi)); return r;
}
__device__ __forceinline__ void unpack2(float& lo, float& hi, u64 a) {
    asm("mov.b64 {%0,%1}, %2;" : "=f"(lo), "=f"(hi) : "l"(a));
}
__device__ __forceinline__ void mma8(float c[4], const u32 a[4], u32 b0, u32 b1) {
    asm("mma.sync.aligned.m16n8k8.row.col.f32.tf32.tf32.f32 "
        "{%0,%1,%2,%3},{%4,%5,%6,%7},{%8,%9},{%0,%1,%2,%3};"
        : "+f"(c[0]), "+f"(c[1]), "+f"(c[2]), "+f"(c[3])
        : "r"(a[0]), "r"(a[1]), "r"(a[2]), "r"(a[3]), "r"(b0), "r"(b1));
}

// D[64x128] = A[64x128]·B ; A = tf32 smem tile at As_addr (stride RSTRIDE words)
__device__ __forceinline__ void gemm64(u32 As_addr, const u64* __restrict__ Bp,
                                       int mrow, int ncol, int lane, float acc[2][4][4])
{
    const int lq = lane >> 2, lr = lane & 3;
    const int ncg = ncol >> 3;
    #pragma unroll
    for (int ks = 0; ks < 16; ks++) {
        u32 a[2][4];
        #pragma unroll
        for (int mt = 0; mt < 2; mt++) {
            u32 ap = As_addr + (u32)(((mrow + mt * 16 + lq) * RSTRIDE + ks * 8 + lr) * 4);
            a[mt][0] = lds32(ap);
            a[mt][1] = lds32(ap + 8 * RSTRIDE * 4);
            a[mt][2] = lds32(ap + 16);
            a[mt][3] = lds32(ap + 8 * RSTRIDE * 4 + 16);
        }
        u32 b0[4], b1[4];
        #pragma unroll
        for (int nt = 0; nt < 4; nt++)
            ldgB(b0[nt], b1[nt], Bp + (((ncg + nt) * 16 + ks) * 32 + lane));
        #pragma unroll
        for (int mt = 0; mt < 2; mt++)
            #pragma unroll
            for (int nt = 0; nt < 4; nt++)
                mma8(acc[mt][nt], a[mt], b0[nt], b1[nt]);
    }
}

__device__ __forceinline__ void store_kvq(float acc[2][4][4], u32 dst_addr,
                                          const float* __restrict__ bias,
                                          int mrow, int ncol, int lane)
{
    const int lq = lane >> 2, lr = lane & 3;
    #pragma unroll
    for (int nt = 0; nt < 4; nt++) {
        const int c = ncol + nt * 8 + lr * 2;
        const float blo = __ldg(bias + c), bhi = __ldg(bias + c + 1);
        #pragma unroll
        for (int mt = 0; mt < 2; mt++) {
            const int r = mrow + mt * 16 + lq;
            if (r < 49)
                sts64(dst_addr + (u32)((r * RSTRIDE + c) * 4),
                      acc[mt][nt][0] + blo, acc[mt][nt][1] + bhi);
            if (r + 8 < 49)
                sts64(dst_addr + (u32)(((r + 8) * RSTRIDE + c) * 4),
                      acc[mt][nt][2] + blo, acc[mt][nt][3] + bhi);
        }
    }
}

__global__ __launch_bounds__(TPB, 2)
void win_attn_kernel(const float* __restrict__ x,
                     const float* __restrict__ qkv_b,
                     const float* __restrict__ proj_b,
                     const float* __restrict__ bt,
                     float* __restrict__ out)
{
    extern __shared__ char smem[];
    const u32 sbase = (u32)__cvta_generic_to_shared(smem);

    const int t    = threadIdx.x;
    const int wid  = t >> 5;
    const int lane = t & 31;
    const int mrow = (wid >> 2) * 32;      // 0 / 32
    const int ncol = (wid & 3) * 32;       // 0,32,64,96

    const int blk = blockIdx.x;
    const int b   = blk >> 6;
    const int win = blk & 63;
    const int wy  = win >> 3;
    const int wx  = win & 7;
    const long base = (((long)b * 56 + wy * 7) * 56 + wx * 7) * 128;

    // stage bias table
    for (int i = t; i < 676; i += TPB) ((float*)(smem + BT_OFF))[i] = bt[i];

    // stage X (49x128) as tf32 into XQ region
    for (int idx = t; idx < 49 * 32; idx += TPB) {
        int r  = idx >> 5;
        int c4 = idx & 31;
        int iy = r / 7, ix = r - iy * 7;
        const float4 v = *(const float4*)(x + base + ((long)iy * 56 + ix) * 128 + c4 * 4);
        sts128(sbase + XQ_OFF + (u32)((r * RSTRIDE + c4 * 4) * 4),
               cvt_tf32(v.x), cvt_tf32(v.y), cvt_tf32(v.z), cvt_tf32(v.w));
    }
    __syncthreads();

    // ---- K phase ----
    {
        float acc[2][4][4];
        #pragma unroll
        for (int a = 0; a < 2; a++) for (int bq = 0; bq < 4; bq++) for (int c = 0; c < 4; c++) acc[a][bq][c] = 0.f;
        gemm64(sbase + XQ_OFF, g_B + 1 * 8192, mrow, ncol, lane, acc);
        store_kvq(acc, sbase + KS_OFF, qkv_b + 128, mrow, ncol, lane);
    }
    // ---- V phase ----
    {
        float acc[2][4][4];
        #pragma unroll
        for (int a = 0; a < 2; a++) for (int bq = 0; bq < 4; bq++) for (int c = 0; c < 4; c++) acc[a][bq][c] = 0.f;
        gemm64(sbase + XQ_OFF, g_B + 2 * 8192, mrow, ncol, lane, acc);
        store_kvq(acc, sbase + VS_OFF, qkv_b + 256, mrow, ncol, lane);
    }
    // ---- Q phase (writes over X after full-CTA read completion) ----
    {
        float acc[2][4][4];
        #pragma unroll
        for (int a = 0; a < 2; a++) for (int bq = 0; bq < 4; bq++) for (int c = 0; c < 4; c++) acc[a][bq][c] = 0.f;
        gemm64(sbase + XQ_OFF, g_B + 0 * 8192, mrow, ncol, lane, acc);
        __syncthreads();
        store_kvq(acc, sbase + XQ_OFF, qkv_b, mrow, ncol, lane);
    }
    __syncthreads();

    // ---- attention: threads 0..195 = (head, query), fp32 f32x2 ----
    if (t < 196) {
        const int h = t / 49;
        const int i = t - h * 49;
        const int iy = i / 7, ix = i - iy * 7;
        const float scale = 0.17677669529663687f;   // 32^-0.5
        const u64 sc2 = pack2(scale, scale);

        const u32 qa = sbase + XQ_OFF + (u32)((i * RSTRIDE + h * 32) * 4);
        u64 qv[16];
        #pragma unroll
        for (int d = 0; d < 16; d += 2) { lds16(qv[d], qv[d + 1], qa + d * 8); }
        #pragma unroll
        for (int d = 0; d < 16; d++) mul2(qv[d], sc2);   // fold scale into q

        u64 ov[16];
        #pragma unroll
        for (int d = 0; d < 16; d++) ov[d] = 0ull;
        float l = 0.f;

        const u32 kb = sbase + KS_OFF + (u32)(h * 128);
        const u32 vb = sbase + VS_OFF + (u32)(h * 128);
        const u32 bta = sbase + BT_OFF + (u32)(h * 4);

        int jy = 0, jx = 0;
        for (int j = 0; j < 49; j++) {
            const u32 kr = kb + (u32)(j * (RSTRIDE * 4));
            u64 s0 = 0ull, s1 = 0ull, s2 = 0ull, s3 = 0ull;
            #pragma unroll
            for (int dd = 0; dd < 8; dd++) {
                u64 a, bb;
                lds16(a, bb, kr + dd * 16);
                if (dd & 1) { fma2(s2, qv[2 * dd], a); fma2(s3, qv[2 * dd + 1], bb); }
                else        { fma2(s0, qv[2 * dd], a); fma2(s1, qv[2 * dd + 1], bb); }
            }
            float s = (red2(s0) + red2(s1)) + (red2(s2) + red2(s3));
            const int ridx = (iy - jy + 6) * 13 + (ix - jx + 6);
            s += lds32f(bta + (u32)(ridx * 16));
            const float pe = __expf(s);
            l += pe;
            const u64 pp = pack2(pe, pe);
            const u32 vr = vb + (u32)(j * (RSTRIDE * 4));
            #pragma unroll
            for (int dd = 0; dd < 8; dd++) {
                u64 a, bb;
                lds16(a, bb, vr + dd * 16);
                fma2(ov[2 * dd], pp, a);
                fma2(ov[2 * dd + 1], pp, bb);
            }
            if (++jx == 7) { jx = 0; ++jy; }
        }

        // write normalized attn-out as tf32 into the same A-tile slot q came from
        const float inv = 1.f / l;
        #pragma unroll
        for (int dd = 0; dd < 8; dd++) {
            float a0, a1, a2, a3;
            unpack2(a0, a1, ov[2 * dd]);
            unpack2(a2, a3, ov[2 * dd + 1]);
            sts128(qa + dd * 16,
                   cvt_tf32(a0 * inv), cvt_tf32(a1 * inv),
                   cvt_tf32(a2 * inv), cvt_tf32(a3 * inv));
        }
    }
    __syncthreads();

    // ---- proj phase ----
    {
        float acc[2][4][4];
        #pragma unroll
        for (int a = 0; a < 2; a++) for (int bq = 0; bq < 4; bq++) for (int c = 0; c < 4; c++) acc[a][bq][c] = 0.f;
        gemm64(sbase + XQ_OFF, g_B + 3 * 8192, mrow, ncol, lane, acc);

        const int lq = lane >> 2, lr = lane & 3;
        #pragma unroll
        for (int nt = 0; nt < 4; nt++) {
            const int c = ncol + nt * 8 + lr * 2;
            const float blo = __ldg(proj_b + c), bhi = __ldg(proj_b + c + 1);
            #pragma unroll
            for (int mt = 0; mt < 2; mt++) {
                #pragma unroll
                for (int half = 0; half < 2; half++) {
                    const int r = mrow + mt * 16 + lq + half * 8;
                    if (r < 49) {
                        const int iy = r / 7, ix = r - iy * 7;
                        float2 v;
                        v.x = acc[mt][nt][2 * half + 0] + blo;
                        v.y = acc[mt][nt][2 * half + 1] + bhi;
                        *(float2*)(out + base + ((long)iy * 56 + ix) * 128 + c) = v;
                    }
                }
            }
        }
    }
}

extern "C" void kernel_launch(void* const* d_in, const int* in_sizes, int n_in,
                              void* d_out, int out_size)
{
    const float* x      = (const float*)d_in[0];
    const float* qkv_w  = (const float*)d_in[1];
    const float* qkv_b  = (const float*)d_in[2];
    const float* proj_w = (const float*)d_in[3];
    const float* proj_b = (const float*)d_in[4];
    const float* bt     = (const float*)d_in[5];
    float* out = (float*)d_out;

    repack<<<128, 256>>>(qkv_w, proj_w);

    cudaFuncSetAttribute(win_attn_kernel,
                         cudaFuncAttributeMaxDynamicSharedMemorySize, SMB);
    win_attn_kernel<<<4096, TPB, SMB>>>(x, qkv_b, proj_b, bt, out);
}

// round 6
// speedup vs baseline: 3.8593x; 1.4365x over previous
#include <cuda_runtime.h>

typedef unsigned int u32;
typedef unsigned long long u64;

#define TPB 256

// smem byte offsets
#define XQ_OFF 0                          // X -> Q -> attn-out A tile: 64 x 132 fp32/tf32
#define KS_OFF 33792                      // K: 56 x 132
#define VS_OFF 63360                      // V: 56 x 132
#define BT_OFF 92928                      // bias table 676 floats
#define SMB    95632
#define P_OFF  0                          // P tiles: 4 heads x 64 x 60 (overlaps XQ+KS, ends 61440)

// pre-packed B fragments: [phase q,k,v,proj][ntile 16][kstep 16][lane 32] -> u64(b0,b1)
__device__ u64 g_B[4 * 8192];

__device__ __forceinline__ u32 cvt_tf32(float f) {
    u32 u; asm("cvt.rna.tf32.f32 %0, %1;" : "=r"(u) : "f"(f)); return u;
}

__global__ void repack(const float* __restrict__ qw, const float* __restrict__ pw)
{
    int i = blockIdx.x * 256 + threadIdx.x;       // 32768 total
    if (i >= 32768) return;
    int phase = i >> 13;
    int rem   = i & 8191;
    int nt    = rem >> 9;
    int ks    = (rem >> 5) & 15;
    int lane  = rem & 31;
    int k0 = ks * 8 + (lane & 3);
    int n  = nt * 8 + (lane >> 2);
    float f0, f1;
    if (phase < 3) { f0 = qw[k0 * 384 + phase * 128 + n]; f1 = qw[(k0 + 4) * 384 + phase * 128 + n]; }
    else           { f0 = pw[k0 * 128 + n];               f1 = pw[(k0 + 4) * 128 + n]; }
    g_B[i] = ((u64)cvt_tf32(f1) << 32) | (u64)cvt_tf32(f0);
}

// ---------------- helpers ----------------
__device__ __forceinline__ u32 lds32(u32 a) {
    u32 v; asm volatile("ld.shared.b32 %0, [%1];" : "=r"(v) : "r"(a)); return v;
}
__device__ __forceinline__ float lds32f(u32 a) {
    float v; asm volatile("ld.shared.f32 %0, [%1];" : "=f"(v) : "r"(a)); return v;
}
__device__ __forceinline__ void sts64u(u32 a, u32 x, u32 y) {
    asm volatile("st.shared.v2.b32 [%0], {%1,%2};" :: "r"(a), "r"(x), "r"(y) : "memory");
}
__device__ __forceinline__ void sts128(u32 a, u32 x, u32 y, u32 z, u32 w) {
    asm volatile("st.shared.v4.b32 [%0], {%1,%2,%3,%4};" :: "r"(a), "r"(x), "r"(y), "r"(z), "r"(w) : "memory");
}
__device__ __forceinline__ void ldgB(u32& b0, u32& b1, const u64* p) {
    asm volatile("ld.global.nc.v2.u32 {%0,%1}, [%2];" : "=r"(b0), "=r"(b1) : "l"(p));
}
__device__ __forceinline__ void mma8(float c[4], const u32 a[4], u32 b0, u32 b1) {
    asm("mma.sync.aligned.m16n8k8.row.col.f32.tf32.tf32.f32 "
        "{%0,%1,%2,%3},{%4,%5,%6,%7},{%8,%9},{%0,%1,%2,%3};"
        : "+f"(c[0]), "+f"(c[1]), "+f"(c[2]), "+f"(c[3])
        : "r"(a[0]), "r"(a[1]), "r"(a[2]), "r"(a[3]), "r"(b0), "r"(b1));
}

// D[64x128] = A[64x128]·B ; A = tf32 smem tile (stride 132 words)
__device__ __forceinline__ void gemm64(u32 As_addr, const u64* __restrict__ Bp,
                                       int mrow, int ncol, int lane, float acc[2][4][4])
{
    const int lq = lane >> 2, lr = lane & 3;
    const int ncg = ncol >> 3;
    #pragma unroll
    for (int ks = 0; ks < 16; ks++) {
        u32 a[2][4];
        #pragma unroll
        for (int mt = 0; mt < 2; mt++) {
            u32 ap = As_addr + (u32)(((mrow + mt * 16 + lq) * 132 + ks * 8 + lr) * 4);
            a[mt][0] = lds32(ap);
            a[mt][1] = lds32(ap + 8 * 132 * 4);
            a[mt][2] = lds32(ap + 16);
            a[mt][3] = lds32(ap + 8 * 132 * 4 + 16);
        }
        u32 b0[4], b1[4];
        #pragma unroll
        for (int nt = 0; nt < 4; nt++)
            ldgB(b0[nt], b1[nt], Bp + (((ncg + nt) * 16 + ks) * 32 + lane));
        #pragma unroll
        for (int mt = 0; mt < 2; mt++)
            #pragma unroll
            for (int nt = 0; nt < 4; nt++)
                mma8(acc[mt][nt], a[mt], b0[nt], b1[nt]);
    }
}

// store K/V/Q tiles as tf32 (feed later mmas), rows < 49 only
__device__ __forceinline__ void store_kvq(float acc[2][4][4], u32 dst_addr,
                                          const float* __restrict__ bias,
                                          int mrow, int ncol, int lane)
{
    const int lq = lane >> 2, lr = lane & 3;
    #pragma unroll
    for (int nt = 0; nt < 4; nt++) {
        const int c = ncol + nt * 8 + lr * 2;
        const float blo = __ldg(bias + c), bhi = __ldg(bias + c + 1);
        #pragma unroll
        for (int mt = 0; mt < 2; mt++) {
            const int r = mrow + mt * 16 + lq;
            if (r < 49)
                sts64u(dst_addr + (u32)((r * 132 + c) * 4),
                       cvt_tf32(acc[mt][nt][0] + blo), cvt_tf32(acc[mt][nt][1] + bhi));
            if (r + 8 < 49)
                sts64u(dst_addr + (u32)(((r + 8) * 132 + c) * 4),
                       cvt_tf32(acc[mt][nt][2] + blo), cvt_tf32(acc[mt][nt][3] + bhi));
        }
    }
}

__global__ __launch_bounds__(TPB, 2)
void win_attn_kernel(const float* __restrict__ x,
                     const float* __restrict__ qkv_b,
                     const float* __restrict__ proj_b,
                     const float* __restrict__ bt,
                     float* __restrict__ out)
{
    extern __shared__ char smem[];
    const u32 sbase = (u32)__cvta_generic_to_shared(smem);
    const u32 XQ_a = sbase + XQ_OFF;
    const u32 KS_a = sbase + KS_OFF;
    const u32 VS_a = sbase + VS_OFF;
    const u32 BT_a = sbase + BT_OFF;

    const int t    = threadIdx.x;
    const int wid  = t >> 5;
    const int lane = t & 31;
    const int lq   = lane >> 2, lr = lane & 3;
    const int mrow = (wid >> 2) * 32;      // linear-gemm m tile
    const int ncol = (wid & 3) * 32;       // linear-gemm n tile

    const int blk = blockIdx.x;
    const int b   = blk >> 6;
    const int win = blk & 63;
    const int wy  = win >> 3;
    const int wx  = win & 7;
    const long base = (((long)b * 56 + wy * 7) * 56 + wx * 7) * 128;

    // stage bias table; zero V padding rows 49..55
    for (int i = t; i < 676; i += TPB) ((float*)(smem + BT_OFF))[i] = bt[i];
    for (int i = t; i < 7 * 132; i += TPB) ((float*)(smem + VS_OFF))[49 * 132 + i] = 0.f;

    // stage X (49x128) as tf32 into XQ
    for (int idx = t; idx < 49 * 32; idx += TPB) {
        int r  = idx >> 5;
        int c4 = idx & 31;
        int iy = r / 7, ix = r - iy * 7;
        const float4 v = *(const float4*)(x + base + ((long)iy * 56 + ix) * 128 + c4 * 4);
        sts128(XQ_a + (u32)((r * 132 + c4 * 4) * 4),
               cvt_tf32(v.x), cvt_tf32(v.y), cvt_tf32(v.z), cvt_tf32(v.w));
    }
    __syncthreads();

    // ---- K phase ----
    {
        float acc[2][4][4];
        #pragma unroll
        for (int a = 0; a < 2; a++) for (int q = 0; q < 4; q++) for (int c = 0; c < 4; c++) acc[a][q][c] = 0.f;
        gemm64(XQ_a, g_B + 1 * 8192, mrow, ncol, lane, acc);
        store_kvq(acc, KS_a, qkv_b + 128, mrow, ncol, lane);
    }
    // ---- V phase ----
    {
        float acc[2][4][4];
        #pragma unroll
        for (int a = 0; a < 2; a++) for (int q = 0; q < 4; q++) for (int c = 0; c < 4; c++) acc[a][q][c] = 0.f;
        gemm64(XQ_a, g_B + 2 * 8192, mrow, ncol, lane, acc);
        store_kvq(acc, VS_a, qkv_b + 256, mrow, ncol, lane);
    }
    // ---- Q phase (overwrites XQ after CTA-wide read completion) ----
    {
        float acc[2][4][4];
        #pragma unroll
        for (int a = 0; a < 2; a++) for (int q = 0; q < 4; q++) for (int c = 0; c < 4; c++) acc[a][q][c] = 0.f;
        gemm64(XQ_a, g_B + 0 * 8192, mrow, ncol, lane, acc);
        __syncthreads();
        store_kvq(acc, XQ_a, qkv_b, mrow, ncol, lane);
    }
    __syncthreads();

    // ================= attention via mma: warp = (head h2, m-half msel) =================
    const int h2   = wid >> 1;
    const int msel = wid & 1;
    const int mra  = msel * 32;
    const u32 P_a  = sbase + P_OFF + (u32)(h2 * 15360);    // 64 x 60 fp32/tf32, stride 60
    const float scale = 0.17677669529663687f;              // 32^-0.5

    // per-thread row coords (4 row slots)
    int rows[4], iy4[4], ix4[4];
    #pragma unroll
    for (int s = 0; s < 4; s++) {
        rows[s] = mra + (s >> 1) * 16 + lq + (s & 1) * 8;
        int ii = min(rows[s], 48);
        iy4[s] = ii / 7; ix4[s] = ii - iy4[s] * 7;
    }

    // ---- S = Q·K^T  (M=32 rows, N=56 cols, K=32) ----
    float sacc[2][7][4];
    #pragma unroll
    for (int a = 0; a < 2; a++) for (int q = 0; q < 7; q++) for (int c = 0; c < 4; c++) sacc[a][q][c] = 0.f;
    #pragma unroll
    for (int ks = 0; ks < 4; ks++) {
        u32 a[2][4];
        #pragma unroll
        for (int mt = 0; mt < 2; mt++) {
            u32 ap = XQ_a + (u32)(((mra + mt * 16 + lq) * 132 + h2 * 32 + ks * 8 + lr) * 4);
            a[mt][0] = lds32(ap);
            a[mt][1] = lds32(ap + 8 * 132 * 4);
            a[mt][2] = lds32(ap + 16);
            a[mt][3] = lds32(ap + 8 * 132 * 4 + 16);
        }
        #pragma unroll
        for (int nt = 0; nt < 7; nt++) {
            u32 bp = KS_a + (u32)(((nt * 8 + lq) * 132 + h2 * 32 + ks * 8 + lr) * 4);
            u32 b0 = lds32(bp), b1 = lds32(bp + 16);
            mma8(sacc[0][nt], a[0], b0, b1);
            mma8(sacc[1][nt], a[1], b0, b1);
        }
    }
    __syncthreads();   // all warps done reading Q/K before P overwrites that region

    // ---- softmax on fragments; store unnormalized P (tf32) ----
    float part[4] = {0.f, 0.f, 0.f, 0.f};
    #pragma unroll
    for (int nt = 0; nt < 7; nt++) {
        const int col0 = nt * 8 + 2 * lr;
        const int jj0 = min(col0, 48), jj1 = min(col0 + 1, 48);
        const int jy0 = jj0 / 7, jx0 = jj0 - jy0 * 7;
        const int jy1 = jj1 / 7, jx1 = jj1 - jy1 * 7;
        const bool v0 = col0 < 49, v1 = col0 + 1 < 49;
        #pragma unroll
        for (int mt = 0; mt < 2; mt++) {
            const int sa = 2 * mt, sb = 2 * mt + 1;
            float b00 = lds32f(BT_a + (u32)((((iy4[sa] - jy0 + 6) * 13 + ix4[sa] - jx0 + 6) * 4 + h2) * 4));
            float b01 = lds32f(BT_a + (u32)((((iy4[sa] - jy1 + 6) * 13 + ix4[sa] - jx1 + 6) * 4 + h2) * 4));
            float b10 = lds32f(BT_a + (u32)((((iy4[sb] - jy0 + 6) * 13 + ix4[sb] - jx0 + 6) * 4 + h2) * 4));
            float b11 = lds32f(BT_a + (u32)((((iy4[sb] - jy1 + 6) * 13 + ix4[sb] - jx1 + 6) * 4 + h2) * 4));
            float p0 = v0 ? __expf(fmaf(sacc[mt][nt][0], scale, b00)) : 0.f;
            float p1 = v1 ? __expf(fmaf(sacc[mt][nt][1], scale, b01)) : 0.f;
            float p2 = v0 ? __expf(fmaf(sacc[mt][nt][2], scale, b10)) : 0.f;
            float p3 = v1 ? __expf(fmaf(sacc[mt][nt][3], scale, b11)) : 0.f;
            part[sa] += p0 + p1;
            part[sb] += p2 + p3;
            sts64u(P_a + (u32)((rows[sa] * 60 + col0) * 4), cvt_tf32(p0), cvt_tf32(p1));
            sts64u(P_a + (u32)((rows[sb] * 60 + col0) * 4), cvt_tf32(p2), cvt_tf32(p3));
        }
    }
    __syncwarp();      // cross-lane visibility of this warp's P stores

    float inv[4];
    #pragma unroll
    for (int s = 0; s < 4; s++) {
        float l = part[s];
        l += __shfl_xor_sync(0xffffffffu, l, 1);
        l += __shfl_xor_sync(0xffffffffu, l, 2);
        inv[s] = 1.f / l;
    }

    // ---- O = P·V  (M=32 rows, N=32 dims, K=56) ----
    float oacc[2][4][4];
    #pragma unroll
    for (int a = 0; a < 2; a++) for (int q = 0; q < 4; q++) for (int c = 0; c < 4; c++) oacc[a][q][c] = 0.f;
    #pragma unroll
    for (int ks = 0; ks < 7; ks++) {
        u32 a[2][4];
        #pragma unroll
        for (int mt = 0; mt < 2; mt++) {
            u32 ap = P_a + (u32)(((mra + mt * 16 + lq) * 60 + ks * 8 + lr) * 4);
            a[mt][0] = lds32(ap);
            a[mt][1] = lds32(ap + 8 * 60 * 4);
            a[mt][2] = lds32(ap + 16);
            a[mt][3] = lds32(ap + 8 * 60 * 4 + 16);
        }
        #pragma unroll
        for (int nt = 0; nt < 4; nt++) {
            u32 bp = VS_a + (u32)(((ks * 8 + lr) * 132 + h2 * 32 + nt * 8 + lq) * 4);
            u32 b0 = lds32(bp), b1 = lds32(bp + 4 * 132 * 4);
            mma8(oacc[0][nt], a[0], b0, b1);
            mma8(oacc[1][nt], a[1], b0, b1);
        }
    }
    __syncthreads();   // all P·V reads done before O overwrites XQ/P region

    // ---- O epilogue: normalize, cvt tf32, store as proj A tile ----
    #pragma unroll
    for (int mt = 0; mt < 2; mt++) {
        #pragma unroll
        for (int nt = 0; nt < 4; nt++) {
            const int col = h2 * 32 + nt * 8 + 2 * lr;
            u32 ra = XQ_a + (u32)(((mra + mt * 16 + lq) * 132 + col) * 4);
            sts64u(ra, cvt_tf32(oacc[mt][nt][0] * inv[2 * mt]),
                       cvt_tf32(oacc[mt][nt][1] * inv[2 * mt]));
            sts64u(ra + 8 * 132 * 4, cvt_tf32(oacc[mt][nt][2] * inv[2 * mt + 1]),
                                     cvt_tf32(oacc[mt][nt][3] * inv[2 * mt + 1]));
        }
    }
    __syncthreads();

    // ---- proj phase ----
    {
        float acc[2][4][4];
        #pragma unroll
        for (int a = 0; a < 2; a++) for (int q = 0; q < 4; q++) for (int c = 0; c < 4; c++) acc[a][q][c] = 0.f;
        gemm64(XQ_a, g_B + 3 * 8192, mrow, ncol, lane, acc);

        #pragma unroll
        for (int nt = 0; nt < 4; nt++) {
            const int c = ncol + nt * 8 + lr * 2;
            const float blo = __ldg(proj_b + c), bhi = __ldg(proj_b + c + 1);
            #pragma unroll
            for (int mt = 0; mt < 2; mt++) {
                #pragma unroll
                for (int half = 0; half < 2; half++) {
                    const int r = mrow + mt * 16 + lq + half * 8;
                    if (r < 49) {
                        const int iy = r / 7, ix = r - iy * 7;
                        float2 v;
                        v.x = acc[mt][nt][2 * half + 0] + blo;
                        v.y = acc[mt][nt][2 * half + 1] + bhi;
                        *(float2*)(out + base + ((long)iy * 56 + ix) * 128 + c) = v;
                    }
                }
            }
        }
    }
}

extern "C" void kernel_launch(void* const* d_in, const int* in_sizes, int n_in,
                              void* d_out, int out_size)
{
    const float* x      = (const float*)d_in[0];
    const float* qkv_w  = (const float*)d_in[1];
    const float* qkv_b  = (const float*)d_in[2];
    const float* proj_w = (const float*)d_in[3];
    const float* proj_b = (const float*)d_in[4];
    const float* bt     = (const float*)d_in[5];
    float* out = (float*)d_out;

    repack<<<128, 256>>>(qkv_w, proj_w);

    cudaFuncSetAttribute(win_attn_kernel,
                         cudaFuncAttributeMaxDynamicSharedMemorySize, SMB);
    win_attn_kernel<<<4096, TPB, SMB>>>(x, qkv_b, proj_b, bt, out);
}